// round 1
// baseline (speedup 1.0000x reference)
#include <cuda_runtime.h>
#include <cuda_bf16.h>

#define B_ 512
#define T_ 512
#define N_ 64

// One block (64 threads) per batch element.
// Thread j owns output tag-column j and holds exp(trans[:, j]) in registers.
// Forward recursion: alpha'[j] = emit[t,j] + M + log( sum_i exp(alpha[i]-M) * ET[i][j] )
// where M = max_i alpha[i] (single shift per step -> exp(trans) is loop-invariant).
__global__ __launch_bounds__(64) void crf_fwd(
    const float* __restrict__ inputs,   // [B, T, N]
    const float* __restrict__ trans,    // [N, N]
    const int*   __restrict__ tags,     // [B, T]
    const int*   __restrict__ lens,     // [B]
    float*       __restrict__ out)      // [B + N*N]
{
    const int b    = blockIdx.x;
    const int j    = threadIdx.x;       // 0..63
    const int lane = j & 31;
    const int warp = j >> 5;

    __shared__ float Esh[N_];
    __shared__ float wmax[2];
    __shared__ float wsum[2];

    // Passthrough copy of transition_params into the output tuple's 2nd slot.
    // 512 blocks x 8 elems = 4096 elems exactly.
    if (j < 8) {
        const int idx = b * 8 + j;
        out[B_ + idx] = trans[idx];
    }

    // Register-resident exp(trans[:, j]) — fully unrolled, constant-indexed.
    float ET[N_];
#pragma unroll
    for (int i = 0; i < N_; i++) ET[i] = __expf(trans[i * N_ + j]);

    const float* emit = inputs + (size_t)b * T_ * N_;
    const int len = lens[b];
    const int steps = (len > 1) ? (len - 1) : 0;   // last_index = max(0, len-1)

    float alpha = emit[j];                         // t = 0
    float emit_cur = (steps >= 1) ? emit[N_ + j] : 0.0f;   // prefetched emit[t]

    for (int t = 1; t <= steps; t++) {
        // Prefetch next emission early so the LDG overlaps the step body.
        const float emit_nxt = (t < steps) ? emit[(t + 1) * N_ + j] : 0.0f;

        // M = max over all 64 alphas (warp shfl reduce + 2-entry smem combine)
        float m = alpha;
#pragma unroll
        for (int off = 16; off; off >>= 1)
            m = fmaxf(m, __shfl_xor_sync(0xffffffffu, m, off));
        if (lane == 0) wmax[warp] = m;
        __syncthreads();
        const float M = fmaxf(wmax[0], wmax[1]);

        Esh[j] = __expf(alpha - M);
        __syncthreads();

        // GEMV: s_j = sum_i E[i] * ET[i][j]  (E via broadcast LDS.128, ET in regs)
        float a0 = 0.0f, a1 = 0.0f, a2 = 0.0f, a3 = 0.0f;
#pragma unroll
        for (int i = 0; i < N_; i += 4) {
            const float4 e = *reinterpret_cast<const float4*>(&Esh[i]);
            a0 = fmaf(e.x, ET[i + 0], a0);
            a1 = fmaf(e.y, ET[i + 1], a1);
            a2 = fmaf(e.z, ET[i + 2], a2);
            a3 = fmaf(e.w, ET[i + 3], a3);
        }
        alpha = emit_cur + M + __logf((a0 + a1) + (a2 + a3));
        emit_cur = emit_nxt;
        // No extra barrier needed: next iteration's smem writes are each
        // preceded by a barrier that orders them after this iteration's reads.
    }

    // log_norm = logsumexp over final alpha
    float m = alpha;
#pragma unroll
    for (int off = 16; off; off >>= 1)
        m = fmaxf(m, __shfl_xor_sync(0xffffffffu, m, off));
    if (lane == 0) wmax[warp] = m;
    __syncthreads();
    const float Mf = fmaxf(wmax[0], wmax[1]);

    float e = __expf(alpha - Mf);
#pragma unroll
    for (int off = 16; off; off >>= 1)
        e += __shfl_xor_sync(0xffffffffu, e, off);
    if (lane == 0) wsum[warp] = e;
    __syncthreads();
    const float logZ = Mf + __logf(wsum[0] + wsum[1]);

    // Sequence score: unary (t in [0,len)) + binary (t in [1,len)), strided by thread.
    const int* btags = tags + b * T_;
    float sc = 0.0f;
    for (int t = j; t < len; t += N_)
        sc += emit[t * N_ + btags[t]];
    for (int t = j + 1; t < len; t += N_)
        sc += trans[btags[t - 1] * N_ + btags[t]];

#pragma unroll
    for (int off = 16; off; off >>= 1)
        sc += __shfl_xor_sync(0xffffffffu, sc, off);
    __syncthreads();               // wsum reuse: all logZ reads must complete first
    if (lane == 0) wsum[warp] = sc;
    __syncthreads();
    if (j == 0) out[b] = (wsum[0] + wsum[1]) - logZ;
}

extern "C" void kernel_launch(void* const* d_in, const int* in_sizes, int n_in,
                              void* d_out, int out_size) {
    const float* inputs = (const float*)d_in[0];   // [512, 512, 64] f32
    const float* trans  = (const float*)d_in[1];   // [64, 64] f32
    const int*   tags   = (const int*)d_in[2];     // [512, 512] i32
    const int*   lens   = (const int*)d_in[3];     // [512] i32
    float*       out    = (float*)d_out;           // [512 + 4096] f32

    crf_fwd<<<B_, N_>>>(inputs, trans, tags, lens, out);
}

// round 2
// speedup vs baseline: 1.3778x; 1.3778x over previous
#include <cuda_runtime.h>
#include <cuda_bf16.h>

#define B_ 512
#define T_ 512
#define N_ 64

// ---- packed f32x2 helpers (sm_103a) ----
__device__ __forceinline__ void ffma2(unsigned long long &d,
                                      unsigned long long a,
                                      unsigned long long b) {
    asm("fma.rn.f32x2 %0, %1, %2, %0;" : "+l"(d) : "l"(a), "l"(b));
}
__device__ __forceinline__ unsigned long long fadd2(unsigned long long a,
                                                    unsigned long long b) {
    unsigned long long d;
    asm("add.rn.f32x2 %0, %1, %2;" : "=l"(d) : "l"(a), "l"(b));
    return d;
}
__device__ __forceinline__ unsigned long long pack2(float lo, float hi) {
    unsigned long long d;
    asm("mov.b64 %0, {%1, %2};" : "=l"(d) : "f"(lo), "f"(hi));
    return d;
}
__device__ __forceinline__ void unpack2(unsigned long long v, float &lo, float &hi) {
    asm("mov.b64 {%0, %1}, %2;" : "=f"(lo), "=f"(hi) : "l"(v));
}

// One block (64 threads / 2 warps) per batch element. Thread j owns tag-column j
// and holds exp(trans[:, j]) as 32 packed f32x2 registers.
//
// Recursion in local coordinates: aLoc[j] = alpha[j] - Mtot, where every step we
// rebase by r = previous aLoc[0] (any common bounded shift works; spread of alpha
// across tags is bounded by emit+trans spread ~= 20, so exp stays in range).
//   E[i]     = exp(aLoc[i])                                (smem, double-buffered)
//   s_j      = sum_i E[i] * exp(trans[i][j])               (f32x2 GEMV)
//   aLoc'[j] = emit[t,j] + log(s_j) - r ;  Mtot += r
// One __syncthreads per step. No max-reduce.
__global__ __launch_bounds__(64) void crf_fwd(
    const float* __restrict__ inputs,   // [B, T, N]
    const float* __restrict__ trans,    // [N, N]
    const int*   __restrict__ tags,     // [B, T]
    const int*   __restrict__ lens,     // [B]
    float*       __restrict__ out)      // [B + N*N]
{
    const int b    = blockIdx.x;
    const int j    = threadIdx.x;       // 0..63
    const int lane = j & 31;
    const int warp = j >> 5;

    // 68-float rows: [0..63] = E vector, [64] = aLoc[0] of that step.
    // Row stride 272B = 17*16B keeps 16B alignment for v2.u64 loads.
    __shared__ float Esh[2][68];
    __shared__ float wmax[2];
    __shared__ float wsum[2];

    // Passthrough copy of transition_params (512 blocks x 8 elems = 4096).
    if (j < 8) {
        const int idx = b * 8 + j;
        out[B_ + idx] = trans[idx];
    }

    // Register-resident exp(trans[:, j]) packed as f32x2 pairs over i.
    unsigned long long ETp[N_ / 2];
#pragma unroll
    for (int i = 0; i < N_ / 2; i++) {
        const float lo = __expf(trans[(2 * i) * N_ + j]);
        const float hi = __expf(trans[(2 * i + 1) * N_ + j]);
        ETp[i] = pack2(lo, hi);
    }

    const float* emit = inputs + (size_t)b * T_ * N_;
    const int len = lens[b];
    const int steps = (len > 1) ? (len - 1) : 0;   // last_index = max(0, len-1)

    float aLoc = emit[j];                          // t = 0 (Mtot = 0 coords)
    float Mtot = 0.0f;

    // Software prefetch, distance 2.
    float e_c = (steps >= 1) ? emit[1 * N_ + j] : 0.0f;
    float e_n = (steps >= 2) ? emit[2 * N_ + j] : 0.0f;

    for (int t = 1; t <= steps; t++) {
        const float e_nn = (t + 2 <= steps) ? emit[(t + 2) * N_ + j] : 0.0f;
        const int buf = t & 1;

        Esh[buf][j] = __expf(aLoc);
        if (j == 0) Esh[buf][64] = aLoc;
        __syncthreads();

        // GEMV: s_j = sum_i E[i] * ET[i][j], packed f32x2, 4 accumulators.
        unsigned long long a0 = 0ull, a1 = 0ull, a2 = 0ull, a3 = 0ull;
        const ulonglong2* ev = reinterpret_cast<const ulonglong2*>(&Esh[buf][0]);
#pragma unroll
        for (int k = 0; k < 8; k++) {
            const ulonglong2 p = ev[2 * k];       // E[8k..8k+3]
            const ulonglong2 q = ev[2 * k + 1];   // E[8k+4..8k+7]
            ffma2(a0, p.x, ETp[4 * k + 0]);
            ffma2(a1, p.y, ETp[4 * k + 1]);
            ffma2(a2, q.x, ETp[4 * k + 2]);
            ffma2(a3, q.y, ETp[4 * k + 3]);
        }
        const float r = Esh[buf][64];             // common rebase shift

        const unsigned long long sA = fadd2(fadd2(a0, a1), fadd2(a2, a3));
        float slo, shi;
        unpack2(sA, slo, shi);

        aLoc = (e_c + __logf(slo + shi)) - r;
        Mtot += r;
        e_c = e_n;
        e_n = e_nn;
        // Single barrier per step: double buffering makes it safe.
    }

    // log_norm = Mtot + logsumexp over final aLoc (one-time reduce).
    float m = aLoc;
#pragma unroll
    for (int off = 16; off; off >>= 1)
        m = fmaxf(m, __shfl_xor_sync(0xffffffffu, m, off));
    if (lane == 0) wmax[warp] = m;
    __syncthreads();
    const float Mf = fmaxf(wmax[0], wmax[1]);

    float e = __expf(aLoc - Mf);
#pragma unroll
    for (int off = 16; off; off >>= 1)
        e += __shfl_xor_sync(0xffffffffu, e, off);
    if (lane == 0) wsum[warp] = e;
    __syncthreads();
    const float logZ = Mtot + Mf + __logf(wsum[0] + wsum[1]);

    // Sequence score: unary (t in [0,len)) + binary (t in [1,len)).
    const int* btags = tags + b * T_;
    float sc = 0.0f;
    for (int t = j; t < len; t += N_)
        sc += emit[t * N_ + btags[t]];
    for (int t = j + 1; t < len; t += N_)
        sc += trans[btags[t - 1] * N_ + btags[t]];

#pragma unroll
    for (int off = 16; off; off >>= 1)
        sc += __shfl_xor_sync(0xffffffffu, sc, off);
    __syncthreads();               // all logZ reads of wsum must complete first
    if (lane == 0) wsum[warp] = sc;
    __syncthreads();
    if (j == 0) out[b] = (wsum[0] + wsum[1]) - logZ;
}

extern "C" void kernel_launch(void* const* d_in, const int* in_sizes, int n_in,
                              void* d_out, int out_size) {
    const float* inputs = (const float*)d_in[0];   // [512, 512, 64] f32
    const float* trans  = (const float*)d_in[1];   // [64, 64] f32
    const int*   tags   = (const int*)d_in[2];     // [512, 512] i32
    const int*   lens   = (const int*)d_in[3];     // [512] i32
    float*       out    = (float*)d_out;           // [512 + 4096] f32

    crf_fwd<<<B_, N_>>>(inputs, trans, tags, lens, out);
}